// round 7
// baseline (speedup 1.0000x reference)
#include <cuda_runtime.h>
#include <cuda_bf16.h>

// SpatialConsistencyLoss — fused persistent kernel, balanced grid + barrier.
//   original, enhanced: [32,3,512,512] f32
//   p = avg_pool4(mean_c(orig)) - avg_pool4(mean_c(enh))   [32,128,128]
//   loss[i,j] = sum_dirs (p[i,j] - p[nbr])^2, zero-padded  -> [32,1,128,128]
//
// Grid = 592 = 148 SMs x 4 blocks (exact multiple -> perfect wave balance,
// all blocks co-resident so the counter grid-barrier is safe). The 4096
// pooled rows are split flat: blocks 0..543 take 7 rows, 544..591 take 6
// (1.2% imbalance vs 16% for the 512-strip split). Phase 2 reads halos from
// the freshly-written L2-resident scratch; no smem needed.

#define B 32
#define HP 128
#define WP 128
#define NPOOL (B * HP * WP)
#define HIN 512
#define WIN 512
#define CH_STRIDE (HIN * WIN)          // 262144
#define IMG_STRIDE (3 * CH_STRIDE)     // 786432
#define THREADS 256
#define NBLOCKS 592                    // 148 * 4
#define TOTAL_ROWS (B * HP)            // 4096
#define ROWS_BASE (TOTAL_ROWS / NBLOCKS)       // 6
#define BIG_BLOCKS (TOTAL_ROWS - ROWS_BASE * NBLOCKS)  // 544 blocks with 7 rows

__device__ float g_pooled[NPOOL];          // 2 MB scratch
__device__ unsigned int g_arrive = 0;
__device__ unsigned int g_exit   = 0;

__device__ __forceinline__ float sq(float x) { return x * x; }

__global__ __launch_bounds__(THREADS, 4)
void scl_balanced_kernel(const float* __restrict__ orig,
                         const float* __restrict__ enh,
                         float* __restrict__ out) {
    const int k = blockIdx.x;
    int start, nrows;
    if (k < BIG_BLOCKS) { start = k * (ROWS_BASE + 1); nrows = ROWS_BASE + 1; }
    else { start = BIG_BLOCKS * (ROWS_BASE + 1) + (k - BIG_BLOCKS) * ROWS_BASE; nrows = ROWS_BASE; }

    // ---- Phase 1: pooled diff rows [start, start+nrows) -> g_pooled ----
    // One item = one pooled pixel = 24 warp-contiguous LDG.128 (512B/warp/load).
    const int nitems = nrows << 7;
    for (int it = threadIdx.x; it < nitems; it += THREADS) {
        int gr  = start + (it >> 7);       // global pooled row = b*128 + i
        int col = it & (WP - 1);
        int b   = gr >> 7;
        int i   = gr & (HP - 1);

        int base0 = b * IMG_STRIDE + (i * 4) * WIN + col * 4;
        float s = 0.0f;
#pragma unroll
        for (int c = 0; c < 3; ++c) {
            int base = base0 + c * CH_STRIDE;
#pragma unroll
            for (int r = 0; r < 4; ++r) {
                float4 ov = *reinterpret_cast<const float4*>(orig + base + r * WIN);
                float4 ev = *reinterpret_cast<const float4*>(enh  + base + r * WIN);
                s += (ov.x - ev.x) + (ov.y - ev.y) + (ov.z - ev.z) + (ov.w - ev.w);
            }
        }
        g_pooled[(gr << 7) + col] = s * (1.0f / 48.0f);
    }

    // ---- Grid barrier (self-resetting across graph replays) ----
    __syncthreads();
    if (threadIdx.x == 0) {
        __threadfence();                    // publish this block's rows
        atomicAdd(&g_arrive, 1u);
        while (*(volatile unsigned int*)&g_arrive < NBLOCKS) { }
        __threadfence();                    // acquire other blocks' rows
    }
    __syncthreads();

    // ---- Phase 2: loss for the same rows, one float4 per item ----
    const int nq = nrows << 5;
    for (int it = threadIdx.x; it < nq; it += THREADS) {
        int gr   = start + (it >> 5);
        int colq = (it & 31) << 2;
        int i    = gr & (HP - 1);
        int base = (gr << 7) + colq;

        float4 c = *reinterpret_cast<const float4*>(&g_pooled[base]);
        float4 up = (i > 0)
            ? *reinterpret_cast<const float4*>(&g_pooled[base - WP])
            : make_float4(0.f, 0.f, 0.f, 0.f);
        float4 dn = (i < HP - 1)
            ? *reinterpret_cast<const float4*>(&g_pooled[base + WP])
            : make_float4(0.f, 0.f, 0.f, 0.f);
        float left  = (colq > 0)      ? g_pooled[base - 1] : 0.0f;
        float right = (colq < WP - 4) ? g_pooled[base + 4] : 0.0f;

        float4 o;
        o.x = sq(c.x - left) + sq(c.x - c.y)   + sq(c.x - up.x) + sq(c.x - dn.x);
        o.y = sq(c.y - c.x)  + sq(c.y - c.z)   + sq(c.y - up.y) + sq(c.y - dn.y);
        o.z = sq(c.z - c.y)  + sq(c.z - c.w)   + sq(c.z - up.z) + sq(c.z - dn.z);
        o.w = sq(c.w - c.z)  + sq(c.w - right) + sq(c.w - up.w) + sq(c.w - dn.w);

        *reinterpret_cast<float4*>(out + base) = o;
    }

    // ---- Reset barrier counters for the next graph replay ----
    __syncthreads();
    if (threadIdx.x == 0) {
        unsigned int old = atomicAdd(&g_exit, 1u);
        if (old == NBLOCKS - 1) {
            atomicExch(&g_arrive, 0u);
            atomicExch(&g_exit, 0u);
        }
    }
}

extern "C" void kernel_launch(void* const* d_in, const int* in_sizes, int n_in,
                              void* d_out, int out_size) {
    const float* orig = (const float*)d_in[0];
    const float* enh  = (const float*)d_in[1];
    float* out = (float*)d_out;

    scl_balanced_kernel<<<NBLOCKS, THREADS>>>(orig, enh, out);
}